// round 16
// baseline (speedup 1.0000x reference)
#include <cuda_runtime.h>
#include <cuda_fp16.h>
#include <math.h>
#include <stdint.h>

typedef unsigned long long u64;

// ---------------------------------------------------------------------------
// Output layout (tuple flattened in order)
// ---------------------------------------------------------------------------
#define OFF_OFFSETS 0
#define OFF_SIZES   524288
#define OFF_WEIGHTS 1048576
#define OFF_PREDCLS 1310720
#define OFF_SEG     1310732
#define OFF_SCORE   1572876

// Scratch (device globals; no allocation allowed)
__device__ __half g_f1[33554432];     // feat1 fp16
__device__ __half g_x1[67108864];     // conv1 out fp16
__device__ __half g_x2[67108864];     // conv2 out fp16
__device__ __half g_cp[16777216];     // crops fp16
__device__ __half g_s1[25165824];     // sc1 out fp16
__device__ __half g_s2[25165824];     // sc2 out fp16
// fragment-order fp16 weights (b32-packed)
__device__ __align__(16) __half g_w1[294912];
__device__ __align__(16) __half g_w2[589824];
__device__ __align__(16) __half g_w3[55296];
__device__ __align__(16) __half g_w4[82944];
__device__ int g_cls[4];

// ---------------------------------------------------------------------------
// PTX helpers (arch-generic sm_80+)
// ---------------------------------------------------------------------------
__device__ __forceinline__ uint32_t smem_u32(const void* p) {
    uint32_t a;
    asm("{ .reg .u64 t; cvta.to.shared.u64 t, %1; cvt.u32.u64 %0, t; }"
        : "=r"(a) : "l"(p));
    return a;
}
__device__ __forceinline__ void ldsm_x4(uint32_t* r, uint32_t a) {
    asm volatile("ldmatrix.sync.aligned.m8n8.x4.shared.b16 {%0,%1,%2,%3}, [%4];"
                 : "=r"(r[0]), "=r"(r[1]), "=r"(r[2]), "=r"(r[3]) : "r"(a));
}
__device__ __forceinline__ void mma_f16(float* d, const uint32_t* a, const uint32_t* b) {
    asm volatile("mma.sync.aligned.m16n8k16.row.col.f32.f16.f16.f32 "
                 "{%0,%1,%2,%3}, {%4,%5,%6,%7}, {%8,%9}, {%0,%1,%2,%3};"
                 : "+f"(d[0]), "+f"(d[1]), "+f"(d[2]), "+f"(d[3])
                 : "r"(a[0]), "r"(a[1]), "r"(a[2]), "r"(a[3]),
                   "r"(b[0]), "r"(b[1]));
}
__device__ __forceinline__ void cpa16(uint32_t dst, const void* src, bool ok) {
    int sz = ok ? 16 : 0;
    asm volatile("cp.async.cg.shared.global [%0], [%1], 16, %2;"
                 :: "r"(dst), "l"(src), "r"(sz) : "memory");
}
__device__ __forceinline__ void cp_commit() {
    asm volatile("cp.async.commit_group;" ::: "memory");
}
template <int N>
__device__ __forceinline__ void cp_wait() {
    asm volatile("cp.async.wait_group %0;" :: "n"(N) : "memory");
}

// ---------------------------------------------------------------------------
// Operand preparation kernels
// ---------------------------------------------------------------------------
__global__ void fcvt16_kernel(const float* __restrict__ src,
                              __half* __restrict__ o, int n) {
    int i = blockIdx.x * blockDim.x + threadIdx.x;
    if (i * 4 >= n) return;
    float4 v = *(const float4*)(src + i * 4);
    __half2 a = __halves2half2(__float2half_rn(v.x), __float2half_rn(v.y));
    __half2 b = __halves2half2(__float2half_rn(v.z), __float2half_rn(v.w));
    *(uint2*)(o + i * 4) = make_uint2(*(uint32_t*)&a, *(uint32_t*)&b);
}

// weights [K9][COUT] fp32 -> mma B-fragment order, b32-packed
__global__ void wfrag_kernel(const float* __restrict__ w,
                             uint32_t* __restrict__ o,
                             int K9, int COUT, int CT, int NF, int KH, int total) {
    int i = blockIdx.x * blockDim.x + threadIdx.x;
    if (i >= total) return;
    int r  = i & 1;
    int ni = (i >> 1) % NF;
    int l  = (i >> 1) / NF % 32;
    int nw = (i >> 1) / NF / 32 & 1;
    int kh = (i >> 1) / NF / 64 % KH;
    int nt = (i >> 1) / NF / 64 / KH;
    int k  = kh * 16 + r * 8 + (l & 3) * 2;
    int co = nt * CT + nw * (CT / 2) + ni * 8 + (l >> 2);
    __half2 v = __halves2half2(__float2half_rn(w[(size_t)k * COUT + co]),
                               __float2half_rn(w[(size_t)(k + 1) * COUT + co]));
    o[i] = *(uint32_t*)&v;
}

// ---------------------------------------------------------------------------
// FP16 tensor-core 3x3 SAME conv, HALO-TILED A staging, 3-stage cp.async
// pipeline, FULLY UNROLLED tap loop (ptxas software-pipelines ldsm/LDG).
// MAXB=1 on the big convs: 1 warp/SMSP -> issue demand < MMA-pipe slots.
// ---------------------------------------------------------------------------
#define HALO_SZ (180 * 80)   // 14400 B per buffer

template <int CIN, int COUT_TILE, bool OUT_HALF, int MAXB>
__global__ __launch_bounds__(128, MAXB)
void conv3x3_halo(const __half* __restrict__ in,
                  const uint32_t* __restrict__ wfrag,
                  const float* __restrict__ bias,
                  float* __restrict__ outf, __half* __restrict__ outh,
                  int H, int W, int COUT, int NT) {
    constexpr int CC = CIN / 32;
    constexpr int KH = 9 * CIN / 16;
    constexpr int NF = COUT_TILE / 16;
    extern __shared__ char sm[];
    const uint32_t sb = smem_u32(sm);
    __shared__ float sbias[COUT_TILE];

    int t = threadIdx.x, warp = t >> 5, lane = t & 31;
    int img = blockIdx.z / NT, ntile = blockIdx.z % NT;
    int cobase = ntile * COUT_TILE;
    int x0 = blockIdx.x * 16, y0 = blockIdx.y * 8;

    if (t < COUT_TILE) sbias[t] = bias[cobase + t];

    int wm = warp & 1, nw = warp >> 1;
    int nbase = nw * (COUT_TILE / 2);

    const uint32_t* wbase = wfrag
        + ((size_t)((ntile * KH) * 2 + nw) * 32 + lane) * (2 * NF);
    const size_t whstep = (size_t)128 * NF;

    float acc[4][NF][4];
    #pragma unroll
    for (int i = 0; i < 4; i++)
        #pragma unroll
        for (int j = 0; j < NF; j++)
            #pragma unroll
            for (int q = 0; q < 4; q++) acc[i][j][q] = 0.f;

    const __half* img0 = in + (size_t)img * H * W * CIN;

    auto issue = [&](int cc, int buf) {
        uint32_t AO = sb + buf * HALO_SZ;
        for (int p = t; p < 180; p += 128) {
            int hy = p / 18, hx = p % 18;
            int gy = y0 - 1 + hy, gx = x0 - 1 + hx;
            bool aok = (gy >= 0 && gy < H && gx >= 0 && gx < W);
            int cy = min(max(gy, 0), H - 1), cx = min(max(gx, 0), W - 1);
            const __half* src = img0 + ((size_t)cy * W + cx) * CIN + cc * 32;
            uint32_t dst = AO + (uint32_t)p * 80;
            #pragma unroll
            for (int j = 0; j < 4; j++)
                cpa16(dst + j * 16, src + j * 8, aok);
        }
        cp_commit();
    };

    issue(0, 0);
    if (CC > 1) issue(1, 1);

    // per-lane A base addresses (tap-invariant part)
    uint32_t abase[4];
    #pragma unroll
    for (int mi = 0; mi < 4; mi++) {
        int p = wm * 64 + mi * 16 + (lane & 15);
        int py = p >> 4, px = p & 15;
        abase[mi] = (uint32_t)(((py + 1) * 18 + (px + 1)) * 80 + (lane >> 4) * 16);
    }

    for (int cc = 0; cc < CC; cc++) {
        if (cc + 1 < CC) cp_wait<1>();
        else             cp_wait<0>();
        __syncthreads();
        if (cc + 2 < CC) issue(cc + 2, (cc + 2) % 3);

        uint32_t AO = sb + (cc % 3) * HALO_SZ;
        const uint32_t* wcc = wbase + (size_t)(cc * 2) * whstep;

        #pragma unroll
        for (int tap = 0; tap < 9; tap++) {
            const int dy = tap / 3 - 1, dx = tap % 3 - 1;
            const int hoff = (dy * 18 + dx) * 80;
            #pragma unroll
            for (int k16 = 0; k16 < 2; k16++) {
                const uint32_t* wp = wcc
                    + (size_t)(tap * (CIN / 16) + k16) * whstep;
                uint32_t bh[NF][2];
                if constexpr (NF % 4 == 0) {
                    #pragma unroll
                    for (int j = 0; j < NF / 2; j++) {
                        uint4 v = ((const uint4*)wp)[j];
                        bh[2 * j][0] = v.x;     bh[2 * j][1] = v.y;
                        bh[2 * j + 1][0] = v.z; bh[2 * j + 1][1] = v.w;
                    }
                } else {
                    #pragma unroll
                    for (int j = 0; j < NF; j++) {
                        uint2 v = ((const uint2*)wp)[j];
                        bh[j][0] = v.x; bh[j][1] = v.y;
                    }
                }
                uint32_t ah[4][4];
                #pragma unroll
                for (int mi = 0; mi < 4; mi++)
                    ldsm_x4(ah[mi], AO + abase[mi] + hoff + k16 * 32);
                #pragma unroll
                for (int mi = 0; mi < 4; mi++)
                    #pragma unroll
                    for (int ni = 0; ni < NF; ni++)
                        mma_f16(acc[mi][ni], ah[mi], bh[ni]);
            }
        }
    }

    #pragma unroll
    for (int mi = 0; mi < 4; mi++) {
        int p0 = wm * 64 + mi * 16 + (lane >> 2);
        #pragma unroll
        for (int half_ = 0; half_ < 2; half_++) {
            int p = p0 + half_ * 8;
            int gy = y0 + (p >> 4), gx = x0 + (p & 15);
            size_t pixoff = ((size_t)img * H * W + (size_t)gy * W + gx) * COUT + cobase;
            #pragma unroll
            for (int ni = 0; ni < NF; ni++) {
                int cl = nbase + ni * 8 + (lane & 3) * 2;
                float r0 = acc[mi][ni][half_ * 2 + 0] + sbias[cl];
                float r1 = acc[mi][ni][half_ * 2 + 1] + sbias[cl + 1];
                r0 = fmaxf(r0, 0.f); r1 = fmaxf(r1, 0.f);
                if (OUT_HALF) {
                    __half2 hh = __halves2half2(__float2half_rn(r0), __float2half_rn(r1));
                    *(uint32_t*)(outh + pixoff + cl) = *(uint32_t*)&hh;
                } else {
                    *(float2*)(outf + pixoff + cl) = make_float2(r0, r1);
                }
            }
        }
    }
}

// ---------------------------------------------------------------------------
// Classification head
// ---------------------------------------------------------------------------
__global__ void cls_kernel(const float* __restrict__ feat5,
                           const float* __restrict__ fc1_w, const float* __restrict__ fc1_b,
                           const float* __restrict__ fc2_w, const float* __restrict__ fc2_b,
                           const float* __restrict__ fc3_w, const float* __restrict__ fc3_b,
                           float* __restrict__ out_predcls, int* __restrict__ cls) {
    int b = blockIdx.x;
    int t = threadIdx.x;
    __shared__ float g0[256], g1[256], lg[3];
    const float* f = feat5 + (size_t)b * 16 * 16 * 256;
    float s = 0.f;
    #pragma unroll 4
    for (int p = 0; p < 256; p++) s += f[p * 256 + t];
    g0[t] = s * (1.0f / 256.0f);
    __syncthreads();
    float a = fc1_b[t];
    #pragma unroll 4
    for (int k = 0; k < 256; k++) a = fmaf(g0[k], fc1_w[k * 256 + t], a);
    g1[t] = fmaxf(a, 0.f);
    __syncthreads();
    a = fc2_b[t];
    #pragma unroll 4
    for (int k = 0; k < 256; k++) a = fmaf(g1[k], fc2_w[k * 256 + t], a);
    g0[t] = fmaxf(a, 0.f);
    __syncthreads();
    if (t < 3) {
        a = fc3_b[t];
        for (int k = 0; k < 256; k++) a = fmaf(g0[k], fc3_w[k * 3 + t], a);
        lg[t] = a;
    }
    __syncthreads();
    if (t == 0) {
        float m = fmaxf(lg[0], fmaxf(lg[1], lg[2]));
        float e0 = expf(lg[0] - m), e1 = expf(lg[1] - m), e2 = expf(lg[2] - m);
        float inv = 1.f / (e0 + e1 + e2);
        out_predcls[b * 3 + 0] = e0 * inv;
        out_predcls[b * 3 + 1] = e1 * inv;
        out_predcls[b * 3 + 2] = e2 * inv;
        int c = 0;
        if (lg[1] > lg[0]) c = 1;
        if (lg[2] > lg[c]) c = 2;
        cls[b] = c;
    }
}

// ---------------------------------------------------------------------------
// Fused reg/wt conv, halo-tiled smem staging of fp16 x2 (64-ch chunks).
// ---------------------------------------------------------------------------
#define REG_PITCH 72
#define REG_DSM   (324 * REG_PITCH * 2)   // 46656 B

__global__ __launch_bounds__(256)
void regsel_kernel(const __half* __restrict__ x,
                   const float* __restrict__ reg_w, const float* __restrict__ reg_b,
                   const float* __restrict__ wt_w,  const float* __restrict__ wt_b,
                   const int* __restrict__ cls, float* __restrict__ out) {
    int b = blockIdx.z;
    int c = cls[b];
    extern __shared__ __align__(16) char dsm[];
    __half* tile = (__half*)dsm;
    __shared__ __align__(16) float ws[9 * 256 * 5];
    int t = threadIdx.x;
    for (int i = t; i < 9 * 256; i += 256) {
        const float* rp = reg_w + (size_t)i * 12 + 4 * c;
        float* wp = ws + i * 5;
        wp[0] = rp[0]; wp[1] = rp[1]; wp[2] = rp[2]; wp[3] = rp[3];
        wp[4] = wt_w[(size_t)i * 3 + c];
    }
    int px = t & 15, py = t >> 4;
    int bx0 = blockIdx.x * 16, by0 = blockIdx.y * 16;
    float a0 = reg_b[4 * c], a1 = reg_b[4 * c + 1], a2 = reg_b[4 * c + 2],
          a3 = reg_b[4 * c + 3], a4 = wt_b[c];
    const __half* xi = x + (size_t)b * 256 * 256 * 256;

    for (int cc = 0; cc < 4; cc++) {
        __syncthreads();
        for (int p = t; p < 324; p += 256) {
            int hy = p / 18, hx = p % 18;
            int gy = by0 - 1 + hy, gx = bx0 - 1 + hx;
            bool ok = (gy >= 0 && gy < 256 && gx >= 0 && gx < 256);
            uint4 z = make_uint4(0, 0, 0, 0);
            const uint4* src = (const uint4*)(xi + ((size_t)gy * 256 + gx) * 256 + cc * 64);
            uint4* dst = (uint4*)(tile + p * REG_PITCH);
            #pragma unroll
            for (int j = 0; j < 8; j++) dst[j] = ok ? src[j] : z;
        }
        __syncthreads();
        #pragma unroll
        for (int tap = 0; tap < 9; tap++) {
            int dy = tap / 3 - 1, dx = tap % 3 - 1;
            const __half* ip = tile + ((py + 1 + dy) * 18 + (px + 1 + dx)) * REG_PITCH;
            const float* wp = ws + tap * 256 * 5 + cc * 64 * 5;
            for (int ci = 0; ci < 64; ci += 8) {
                uint4 hv = *(const uint4*)(ip + ci);
                float2 f0 = __half22float2(*(__half2*)&hv.x);
                float2 f1 = __half22float2(*(__half2*)&hv.y);
                float2 f2 = __half22float2(*(__half2*)&hv.z);
                float2 f3 = __half22float2(*(__half2*)&hv.w);
                float v[8] = {f0.x, f0.y, f1.x, f1.y, f2.x, f2.y, f3.x, f3.y};
                const float* wl = wp + ci * 5;
                #pragma unroll
                for (int q = 0; q < 8; q++) {
                    a0 = fmaf(v[q], wl[q * 5 + 0], a0);
                    a1 = fmaf(v[q], wl[q * 5 + 1], a1);
                    a2 = fmaf(v[q], wl[q * 5 + 2], a2);
                    a3 = fmaf(v[q], wl[q * 5 + 3], a3);
                    a4 = fmaf(v[q], wl[q * 5 + 4], a4);
                }
            }
        }
    }
    size_t pix = ((size_t)b * 256 + by0 + py) * 256 + bx0 + px;
    out[OFF_OFFSETS + pix * 2 + 0] = a0;
    out[OFF_OFFSETS + pix * 2 + 1] = a1;
    out[OFF_SIZES   + pix * 2 + 0] = a2;
    out[OFF_SIZES   + pix * 2 + 1] = a3;
    out[OFF_WEIGHTS + pix] = a4;
}

// ---------------------------------------------------------------------------
// Bilinear crop -> fp16
// ---------------------------------------------------------------------------
__global__ void crop_kernel(const float* __restrict__ feat0,
                            const float* __restrict__ boxes,
                            __half* __restrict__ cp) {
    int n = blockIdx.x;
    int b = n >> 6;
    const int H = 512, W = 512, C = 64;
    __shared__ int sy0[32], sx0[32];
    __shared__ float swy[32], swx[32];
    const float* bx = boxes + (size_t)n * 4;
    float y1 = bx[0], x1 = bx[1], y2 = bx[2], x2 = bx[3];
    int t = threadIdx.x;
    if (t < 32) {
        float tt = (float)t / 31.0f;
        float ys = y1 * (H - 1) + tt * (y2 - y1) * (H - 1);
        int yy0 = (int)floorf(ys);
        yy0 = min(max(yy0, 0), H - 2);
        sy0[t] = yy0; swy[t] = ys - (float)yy0;
    } else if (t < 64) {
        int i = t - 32;
        float tt = (float)i / 31.0f;
        float xs = x1 * (W - 1) + tt * (x2 - x1) * (W - 1);
        int xx0 = (int)floorf(xs);
        xx0 = min(max(xx0, 0), W - 2);
        sx0[i] = xx0; swx[i] = xs - (float)xx0;
    }
    __syncthreads();
    const float* f = feat0 + (size_t)b * H * W * C;
    size_t obase = (size_t)n * 32 * 32 * C;
    for (int idx = t; idx < 32 * 32 * C; idx += blockDim.x) {
        int c  = idx & 63;
        int ix = (idx >> 6) & 31;
        int iy = idx >> 11;
        int yy0 = sy0[iy], xx0 = sx0[ix];
        float wy = swy[iy], wx = swx[ix];
        const float* p00 = f + ((size_t)yy0 * W + xx0) * C + c;
        float v00 = p00[0], v01 = p00[C], v10 = p00[(size_t)W * C], v11 = p00[(size_t)W * C + C];
        float top = v00 * (1.f - wx) + v01 * wx;
        float bot = v10 * (1.f - wx) + v11 * wx;
        float v = top * (1.f - wy) + bot * wy;
        cp[obase + idx] = __float2half_rn(v);
    }
}

// ---------------------------------------------------------------------------
// so conv with class selection (1 channel; s2 is fp16)
// ---------------------------------------------------------------------------
__global__ void sosel_kernel(const __half* __restrict__ s2,
                             const float* __restrict__ so_w, const float* __restrict__ so_b,
                             const int* __restrict__ cls, float* __restrict__ out) {
    int n = blockIdx.x;
    int c = cls[n >> 6];
    __shared__ __align__(16) float ws[9 * 96];
    int t = threadIdx.x;
    for (int i = t; i < 864; i += 256) ws[i] = so_w[(size_t)i * 3 + c];
    __syncthreads();
    float bias = so_b[c];
    const __half* sp = s2 + (size_t)n * 32 * 32 * 96;
    for (int pix = t; pix < 1024; pix += 256) {
        int py = pix >> 5, px = pix & 31;
        float acc = bias;
        for (int tap = 0; tap < 9; tap++) {
            int yy = py + tap / 3 - 1, xx = px + tap % 3 - 1;
            if (yy < 0 || yy >= 32 || xx < 0 || xx >= 32) continue;
            const __half* ip = sp + ((size_t)yy * 32 + xx) * 96;
            const float* wp = ws + tap * 96;
            for (int ci = 0; ci < 96; ci += 8) {
                uint4 hv = *(const uint4*)(ip + ci);
                float2 f0 = __half22float2(*(__half2*)&hv.x);
                float2 f1 = __half22float2(*(__half2*)&hv.y);
                float2 f2 = __half22float2(*(__half2*)&hv.z);
                float2 f3 = __half22float2(*(__half2*)&hv.w);
                acc = fmaf(f0.x, wp[ci + 0], acc);
                acc = fmaf(f0.y, wp[ci + 1], acc);
                acc = fmaf(f1.x, wp[ci + 2], acc);
                acc = fmaf(f1.y, wp[ci + 3], acc);
                acc = fmaf(f2.x, wp[ci + 4], acc);
                acc = fmaf(f2.y, wp[ci + 5], acc);
                acc = fmaf(f3.x, wp[ci + 6], acc);
                acc = fmaf(f3.y, wp[ci + 7], acc);
            }
        }
        out[OFF_SEG + (size_t)n * 1024 + pix] = acc;
    }
}

// ---------------------------------------------------------------------------
// Score head: 4 crops per block (4x reuse of sd1_w). s2 is fp16.
// ---------------------------------------------------------------------------
#define SCORE_DSM (4 * 6144 * 4)

__global__ __launch_bounds__(256)
void score_kernel(const __half* __restrict__ s2,
                  const float* __restrict__ sd1_w, const float* __restrict__ sd1_b,
                  const float* __restrict__ sd2_w, const float* __restrict__ sd2_b,
                  const float* __restrict__ sd3_w, const float* __restrict__ sd3_b,
                  const int* __restrict__ cls, float* __restrict__ out) {
    int n0 = blockIdx.x * 4;
    int t = threadIdx.x;
    extern __shared__ __align__(16) char dsm[];
    float* pooled = (float*)dsm;            // [4][6144]
    __shared__ float h1[4][256], h2[4][256];

    for (int o = t; o < 4 * 6144; o += 256) {
        int j  = o / 6144;
        int oo = o % 6144;
        int c  = oo % 96;
        int px = (oo / 96) & 7;
        int py = oo / 768;
        const __half* sp = s2 + (size_t)(n0 + j) * 32 * 32 * 96;
        float s = 0.f;
        #pragma unroll
        for (int i = 0; i < 4; i++)
            #pragma unroll
            for (int q = 0; q < 4; q++)
                s += __half2float(sp[(((size_t)(py * 4 + i)) * 32 + (px * 4 + q)) * 96 + c]);
        pooled[o] = s * (1.f / 16.f);
    }
    __syncthreads();
    {
        float a[4];
        #pragma unroll
        for (int j = 0; j < 4; j++) a[j] = sd1_b[t];
        for (int k = 0; k < 6144; k++) {
            float w = sd1_w[(size_t)k * 256 + t];
            #pragma unroll
            for (int j = 0; j < 4; j++) a[j] = fmaf(pooled[j * 6144 + k], w, a[j]);
        }
        #pragma unroll
        for (int j = 0; j < 4; j++) h1[j][t] = fmaxf(a[j], 0.f);
    }
    __syncthreads();
    {
        float a[4];
        #pragma unroll
        for (int j = 0; j < 4; j++) a[j] = sd2_b[t];
        for (int k = 0; k < 256; k++) {
            float w = sd2_w[k * 256 + t];
            #pragma unroll
            for (int j = 0; j < 4; j++) a[j] = fmaf(h1[j][k], w, a[j]);
        }
        #pragma unroll
        for (int j = 0; j < 4; j++) h2[j][t] = fmaxf(a[j], 0.f);
    }
    __syncthreads();
    if (t < 4) {
        int n = n0 + t;
        int c = cls[n >> 6];
        float acc = sd3_b[c];
        for (int k = 0; k < 256; k++) acc = fmaf(h2[t][k], sd3_w[k * 3 + c], acc);
        out[OFF_SCORE + n] = acc;
    }
}

// ---------------------------------------------------------------------------
extern "C" void kernel_launch(void* const* d_in, const int* in_sizes, int n_in,
                              void* d_out, int out_size) {
    (void)in_sizes; (void)n_in; (void)out_size;
    const float* feat0 = (const float*)d_in[0];
    const float* feat1 = (const float*)d_in[1];
    const float* feat5 = (const float*)d_in[2];
    const float* boxes = (const float*)d_in[3];
    const float* cb1_w = (const float*)d_in[4];
    const float* cb1_b = (const float*)d_in[5];
    const float* cb2_w = (const float*)d_in[6];
    const float* cb2_b = (const float*)d_in[7];
    const float* reg_w = (const float*)d_in[8];
    const float* reg_b = (const float*)d_in[9];
    const float* wt_w  = (const float*)d_in[10];
    const float* wt_b  = (const float*)d_in[11];
    const float* fc1_w = (const float*)d_in[12];
    const float* fc1_b = (const float*)d_in[13];
    const float* fc2_w = (const float*)d_in[14];
    const float* fc2_b = (const float*)d_in[15];
    const float* fc3_w = (const float*)d_in[16];
    const float* fc3_b = (const float*)d_in[17];
    const float* sc1_w = (const float*)d_in[18];
    const float* sc1_b = (const float*)d_in[19];
    const float* sc2_w = (const float*)d_in[20];
    const float* sc2_b = (const float*)d_in[21];
    const float* so_w  = (const float*)d_in[22];
    const float* so_b  = (const float*)d_in[23];
    const float* sd1_w = (const float*)d_in[24];
    const float* sd1_b = (const float*)d_in[25];
    const float* sd2_w = (const float*)d_in[26];
    const float* sd2_b = (const float*)d_in[27];
    const float* sd3_w = (const float*)d_in[28];
    const float* sd3_b = (const float*)d_in[29];
    float* out = (float*)d_out;

    // resolve device globals
    void* p;
    cudaGetSymbolAddress(&p, g_f1);  __half* f1 = (__half*)p;
    cudaGetSymbolAddress(&p, g_x1);  __half* x1 = (__half*)p;
    cudaGetSymbolAddress(&p, g_x2);  __half* x2 = (__half*)p;
    cudaGetSymbolAddress(&p, g_cp);  __half* cp = (__half*)p;
    cudaGetSymbolAddress(&p, g_s1);  __half* s1 = (__half*)p;
    cudaGetSymbolAddress(&p, g_s2);  __half* s2 = (__half*)p;
    cudaGetSymbolAddress(&p, g_w1);  uint32_t* w1 = (uint32_t*)p;
    cudaGetSymbolAddress(&p, g_w2);  uint32_t* w2 = (uint32_t*)p;
    cudaGetSymbolAddress(&p, g_w3);  uint32_t* w3 = (uint32_t*)p;
    cudaGetSymbolAddress(&p, g_w4);  uint32_t* w4 = (uint32_t*)p;
    cudaGetSymbolAddress(&p, g_cls); int* cls = (int*)p;

    constexpr int DYN = 3 * HALO_SZ;   // 43200 (halo A, triple-buffered)
    cudaFuncSetAttribute(conv3x3_halo<128, 128, true, 1>,
                         cudaFuncAttributeMaxDynamicSharedMemorySize, DYN);
    cudaFuncSetAttribute(conv3x3_halo<256, 128, true, 1>,
                         cudaFuncAttributeMaxDynamicSharedMemorySize, DYN);
    cudaFuncSetAttribute(conv3x3_halo<64, 96, true, 3>,
                         cudaFuncAttributeMaxDynamicSharedMemorySize, DYN);
    cudaFuncSetAttribute(conv3x3_halo<96, 96, true, 3>,
                         cudaFuncAttributeMaxDynamicSharedMemorySize, DYN);
    cudaFuncSetAttribute(regsel_kernel,
                         cudaFuncAttributeMaxDynamicSharedMemorySize, REG_DSM);
    cudaFuncSetAttribute(score_kernel,
                         cudaFuncAttributeMaxDynamicSharedMemorySize, SCORE_DSM);

    // classification first (selection depends on cls)
    cls_kernel<<<4, 256>>>(feat5, fc1_w, fc1_b, fc2_w, fc2_b, fc3_w, fc3_b,
                           out + OFF_PREDCLS, cls);

    // operand prep: weights into fragment order; feat1 -> fp16
    wfrag_kernel<<<(147456 + 255) / 256, 256>>>(cb1_w, w1, 1152, 256, 128, 8, 72, 147456);
    wfrag_kernel<<<(294912 + 255) / 256, 256>>>(cb2_w, w2, 2304, 256, 128, 8, 144, 294912);
    wfrag_kernel<<<(27648 + 255) / 256, 256>>>(sc1_w, w3, 576, 96, 96, 6, 36, 27648);
    wfrag_kernel<<<(41472 + 255) / 256, 256>>>(sc2_w, w4, 864, 96, 96, 6, 54, 41472);
    fcvt16_kernel<<<(33554432 / 4 + 255) / 256, 256>>>(feat1, f1, 33554432);

    // crop + segmentation branch
    crop_kernel<<<256, 256>>>(feat0, boxes, cp);
    conv3x3_halo<64, 96, true, 3><<<dim3(2, 4, 256), 128, DYN>>>(
        cp, w3, sc1_b, nullptr, s1, 32, 32, 96, 1);
    conv3x3_halo<96, 96, true, 3><<<dim3(2, 4, 256), 128, DYN>>>(
        s1, w4, sc2_b, nullptr, s2, 32, 32, 96, 1);
    sosel_kernel<<<256, 256>>>(s2, so_w, so_b, cls, out);
    score_kernel<<<64, 256, SCORE_DSM>>>(s2, sd1_w, sd1_b, sd2_w, sd2_b,
                                         sd3_w, sd3_b, cls, out);

    // regression branch (1 CTA/SM: issue-slot headroom for the MMA stream)
    conv3x3_halo<128, 128, true, 1><<<dim3(16, 32, 8), 128, DYN>>>(
        f1, w1, cb1_b, nullptr, x1, 256, 256, 256, 2);
    conv3x3_halo<256, 128, true, 1><<<dim3(16, 32, 8), 128, DYN>>>(
        x1, w2, cb2_b, nullptr, x2, 256, 256, 256, 2);
    regsel_kernel<<<dim3(16, 16, 4), 256, REG_DSM>>>(
        x2, reg_w, reg_b, wt_w, wt_b, cls, out);
}